// round 7
// baseline (speedup 1.0000x reference)
#include <cuda_runtime.h>
#include <cstdint>

#define BATCH    4096
#define FNUM     1024
#define RCNT     19
#define RDIM     1024

#define TPB      (RCNT * 32)        // 608 threads: warp w == relation r
#define ROW      (FNUM * RCNT)      // 19456 floats per batch row
#define ROWB     (ROW * 4)          // 77824 bytes per row (multiple of 16)
#define SMEM_B   (64 + 2 * ROWB)    // 2 mbarriers (+pad) + 2 row buffers

// Precomputed W[f*19 + r] = sum_e U[f,e] * R[r,e]
__device__ float g_W[FNUM * RCNT];

// ---------------------------------------------------------------------------
// Kernel A: W = U @ R^T  (1024 x 19)
// f-tiled x4: each R float4 load is reused for 4 f-rows -> R L2 traffic
// drops 4x (79 MB -> 20 MB).  256 blocks x 256 threads.
// ---------------------------------------------------------------------------
__global__ void __launch_bounds__(256)
compute_w_kernel(const float* __restrict__ U, const float* __restrict__ R) {
    const int f0  = blockIdx.x * 4;
    const int tid = threadIdx.x;                   // 0..255 -> e-slice tid*4
    const float4* U4 = reinterpret_cast<const float4*>(U);
    const float4* R4 = reinterpret_cast<const float4*>(R);

    float4 u[4];
#pragma unroll
    for (int ff = 0; ff < 4; ++ff)
        u[ff] = U4[(size_t)(f0 + ff) * (RDIM / 4) + tid];

    float acc[4][RCNT];
#pragma unroll
    for (int r = 0; r < RCNT; ++r) {
        const float4 rv = R4[(size_t)r * (RDIM / 4) + tid];
#pragma unroll
        for (int ff = 0; ff < 4; ++ff)
            acc[ff][r] = u[ff].x * rv.x + u[ff].y * rv.y
                       + u[ff].z * rv.z + u[ff].w * rv.w;
    }

    // warp tree reduce all 76 partials
#pragma unroll
    for (int ff = 0; ff < 4; ++ff)
#pragma unroll
        for (int r = 0; r < RCNT; ++r) {
            float v = acc[ff][r];
#pragma unroll
            for (int off = 16; off > 0; off >>= 1)
                v += __shfl_down_sync(0xffffffffu, v, off);
            acc[ff][r] = v;
        }

    __shared__ float s_red[8][4][RCNT];
    const int warp = tid >> 5, lane = tid & 31;
    if (lane == 0) {
#pragma unroll
        for (int ff = 0; ff < 4; ++ff)
#pragma unroll
            for (int r = 0; r < RCNT; ++r)
                s_red[warp][ff][r] = acc[ff][r];
    }
    __syncthreads();
    if (tid < 4 * RCNT) {
        const int ff = tid / RCNT, r = tid % RCNT;
        float s = 0.f;
#pragma unroll
        for (int w = 0; w < 8; ++w) s += s_red[w][ff][r];
        g_W[(f0 + ff) * RCNT + r] = s;
    }
}

// ---------------------------------------------------------------------------
// Kernel B: scores[b,r] = sum_f conv[b,f,r] * W[f,r]
// TMA 1D bulk copy (UBLKCP) + mbarrier, double-buffered, 1 CTA/SM persistent.
// Row staged in SMEM, read at stride 19 (gcd(19,32)=1 -> conflict-free).
// Warp == relation, so the reduction is a single intra-warp shuffle tree.
// ---------------------------------------------------------------------------
__global__ void __launch_bounds__(TPB, 1)
score_kernel(const float* __restrict__ conv, float* __restrict__ out) {
    extern __shared__ __align__(16) char smem_raw[];
    // layout: [0,8)=bar0  [8,16)=bar1  [64, 64+2*ROWB) = two row buffers
    const uint32_t s_base = (uint32_t)__cvta_generic_to_shared(smem_raw);
    const uint32_t bar0   = s_base;
    const uint32_t bar1   = s_base + 8;
    const uint32_t buf0   = s_base + 64;
    const uint32_t buf1   = s_base + 64 + ROWB;
    float* sbuf[2] = { (float*)(smem_raw + 64), (float*)(smem_raw + 64 + ROWB) };

    const int tid  = threadIdx.x;
    const int lane = tid & 31;
    const int r    = tid >> 5;                 // warp id == relation id
    const int G    = gridDim.x;

    if (tid == 0) {
        asm volatile("mbarrier.init.shared.b64 [%0], 1;" :: "r"(bar0) : "memory");
        asm volatile("mbarrier.init.shared.b64 [%0], 1;" :: "r"(bar1) : "memory");
    }
    __syncthreads();

    // W values for this (lane, r): reused for every batch row
    float w[32];
#pragma unroll
    for (int k = 0; k < 32; ++k)
        w[k] = g_W[(lane + 32 * k) * RCNT + r];

    // prologue: prefetch first row into buffer 0
    if (tid == 0) {
        asm volatile("mbarrier.arrive.expect_tx.shared.b64 _, [%0], %1;"
                     :: "r"(bar0), "r"((uint32_t)ROWB) : "memory");
        asm volatile(
            "cp.async.bulk.shared::cta.global.mbarrier::complete_tx::bytes "
            "[%0], [%1], %2, [%3];"
            :: "r"(buf0), "l"(conv + (size_t)blockIdx.x * ROW),
               "r"((uint32_t)ROWB), "r"(bar0) : "memory");
    }

    for (int i = 0, b = blockIdx.x; b < BATCH; ++i, b += G) {
        const int cur = i & 1;
        const uint32_t bar_cur = cur ? bar1 : bar0;

        // issue prefetch of next row into the other buffer
        // (its previous compute finished at the end-of-iter barrier of i-1)
        const int nb = b + G;
        if (tid == 0 && nb < BATCH) {
            const uint32_t bar_n = cur ? bar0 : bar1;
            const uint32_t buf_n = cur ? buf0 : buf1;
            asm volatile("mbarrier.arrive.expect_tx.shared.b64 _, [%0], %1;"
                         :: "r"(bar_n), "r"((uint32_t)ROWB) : "memory");
            asm volatile(
                "cp.async.bulk.shared::cta.global.mbarrier::complete_tx::bytes "
                "[%0], [%1], %2, [%3];"
                :: "r"(buf_n), "l"(conv + (size_t)nb * ROW),
                   "r"((uint32_t)ROWB), "r"(bar_n) : "memory");
        }

        // wait for current buffer; buffer `cur` is on its (i>>1)-th use
        {
            const uint32_t parity = (uint32_t)((i >> 1) & 1);
            uint32_t done;
            asm volatile(
                "{\n\t.reg .pred p;\n\t"
                "mbarrier.try_wait.parity.acquire.cta.shared::cta.b64 p, [%1], %2;\n\t"
                "selp.b32 %0, 1, 0, p;\n\t}"
                : "=r"(done) : "r"(bar_cur), "r"(parity) : "memory");
            if (!done) {
                asm volatile(
                    "{\n\t.reg .pred P1;\n\t"
                    "WL_%=:\n\t"
                    "mbarrier.try_wait.parity.acquire.cta.shared::cta.b64 P1, [%0], %1, 0x989680;\n\t"
                    "@P1 bra.uni WD_%=;\n\t"
                    "bra.uni WL_%=;\n\t"
                    "WD_%=:\n\t}"
                    :: "r"(bar_cur), "r"(parity) : "memory");
            }
        }

        // strided SMEM reads: (lane+32k)*19 + r  -> conflict-free
        const float* s_row = sbuf[cur];
        float acc = 0.f;
#pragma unroll
        for (int k = 0; k < 32; ++k)
            acc = fmaf(s_row[(lane + 32 * k) * RCNT + r], w[k], acc);

#pragma unroll
        for (int off = 16; off > 0; off >>= 1)
            acc += __shfl_down_sync(0xffffffffu, acc, off);

        if (lane == 0) out[(size_t)b * RCNT + r] = acc;

        __syncthreads();   // all reads of `cur` done before iter i+1 refills it
    }
}

// ---------------------------------------------------------------------------
extern "C" void kernel_launch(void* const* d_in, const int* in_sizes, int n_in,
                              void* d_out, int out_size) {
    const float* conv = nullptr;
    const float* Rm   = nullptr;
    const float* Um   = nullptr;
    for (int i = 0; i < n_in; ++i) {
        if (in_sizes[i] == BATCH * FNUM * RCNT)      conv = (const float*)d_in[i];
        else if (in_sizes[i] == RCNT * RDIM)         Rm   = (const float*)d_in[i];
        else if (in_sizes[i] == FNUM * RDIM)         Um   = (const float*)d_in[i];
    }
    float* out = (float*)d_out;

    static int attr_done = 0;
    if (!attr_done) {
        cudaFuncSetAttribute(score_kernel,
                             cudaFuncAttributeMaxDynamicSharedMemorySize, SMEM_B);
        attr_done = 1;
    }

    int dev = 0, nsm = 148;
    cudaGetDevice(&dev);
    cudaDeviceGetAttribute(&nsm, cudaDevAttrMultiProcessorCount, dev);

    compute_w_kernel<<<FNUM / 4, 256>>>(Um, Rm);
    score_kernel<<<nsm, TPB, SMEM_B>>>(conv, out);
}

// round 12
// speedup vs baseline: 1.1421x; 1.1421x over previous
#include <cuda_runtime.h>
#include <cstdint>

#define BATCH    4096
#define FNUM     1024
#define RCNT     19
#define RDIM     1024

#define TPB      (RCNT * 32)          // 608 threads: warp w == relation r
#define ROW      (FNUM * RCNT)        // 19456 floats per batch row
#define CH_F     512                  // f's per chunk (2 chunks per row)
#define CH_FL    (CH_F * RCNT)        // 9728 floats per chunk
#define CH_B     (CH_FL * 4)          // 38912 bytes per chunk
#define NSTAGE   2
#define SMEM_B   (128 + NSTAGE * CH_B)  // 77952 B per CTA -> 2 CTAs/SM

// Precomputed W[f*19 + r] = sum_e U[f,e] * R[r,e]
__device__ float g_W[FNUM * RCNT];

// ---------------------------------------------------------------------------
// Kernel A: W = U @ R^T  (1024 x 19), f-tiled x4
// ---------------------------------------------------------------------------
__global__ void __launch_bounds__(256)
compute_w_kernel(const float* __restrict__ U, const float* __restrict__ R) {
    const int f0  = blockIdx.x * 4;
    const int tid = threadIdx.x;
    const float4* U4 = reinterpret_cast<const float4*>(U);
    const float4* R4 = reinterpret_cast<const float4*>(R);

    float4 u[4];
#pragma unroll
    for (int ff = 0; ff < 4; ++ff)
        u[ff] = U4[(size_t)(f0 + ff) * (RDIM / 4) + tid];

    float acc[4][RCNT];
#pragma unroll
    for (int r = 0; r < RCNT; ++r) {
        const float4 rv = R4[(size_t)r * (RDIM / 4) + tid];
#pragma unroll
        for (int ff = 0; ff < 4; ++ff)
            acc[ff][r] = u[ff].x * rv.x + u[ff].y * rv.y
                       + u[ff].z * rv.z + u[ff].w * rv.w;
    }

#pragma unroll
    for (int ff = 0; ff < 4; ++ff)
#pragma unroll
        for (int r = 0; r < RCNT; ++r) {
            float v = acc[ff][r];
#pragma unroll
            for (int off = 16; off > 0; off >>= 1)
                v += __shfl_down_sync(0xffffffffu, v, off);
            acc[ff][r] = v;
        }

    __shared__ float s_red[8][4][RCNT];
    const int warp = tid >> 5, lane = tid & 31;
    if (lane == 0) {
#pragma unroll
        for (int ff = 0; ff < 4; ++ff)
#pragma unroll
            for (int r = 0; r < RCNT; ++r)
                s_red[warp][ff][r] = acc[ff][r];
    }
    __syncthreads();
    if (tid < 4 * RCNT) {
        const int ff = tid / RCNT, r = tid % RCNT;
        float s = 0.f;
#pragma unroll
        for (int w = 0; w < 8; ++w) s += s_red[w][ff][r];
        g_W[(f0 + ff) * RCNT + r] = s;
    }
}

// ---------------------------------------------------------------------------
// mbarrier parity wait (acquire)
// ---------------------------------------------------------------------------
__device__ __forceinline__ void bar_wait(uint32_t bar, uint32_t parity) {
    uint32_t done;
    asm volatile(
        "{\n\t.reg .pred p;\n\t"
        "mbarrier.try_wait.parity.acquire.cta.shared::cta.b64 p, [%1], %2;\n\t"
        "selp.b32 %0, 1, 0, p;\n\t}"
        : "=r"(done) : "r"(bar), "r"(parity) : "memory");
    if (!done) {
        asm volatile(
            "{\n\t.reg .pred P1;\n\t"
            "WL_%=:\n\t"
            "mbarrier.try_wait.parity.acquire.cta.shared::cta.b64 P1, [%0], %1, 0x989680;\n\t"
            "@P1 bra.uni WD_%=;\n\t"
            "bra.uni WL_%=;\n\t"
            "WD_%=:\n\t}"
            :: "r"(bar), "r"(parity) : "memory");
    }
}

__device__ __forceinline__ void tma_fill(uint32_t bar, uint32_t dst,
                                         const float* src) {
    asm volatile("mbarrier.arrive.expect_tx.shared.b64 _, [%0], %1;"
                 :: "r"(bar), "r"((uint32_t)CH_B) : "memory");
    asm volatile(
        "cp.async.bulk.shared::cta.global.mbarrier::complete_tx::bytes "
        "[%0], [%1], %2, [%3];"
        :: "r"(dst), "l"(src), "r"((uint32_t)CH_B), "r"(bar) : "memory");
}

// ---------------------------------------------------------------------------
// Kernel B: scores[b,r] = sum_f conv[b,f,r] * W[f,r]
// TMA half-row chunks, 2-stage pipeline released by __syncthreads.
// 2 CTAs/SM (38 warps). Only full-barriers; refill is issued after the
// sync every warp reaches -> structurally deadlock-free.
// SMEM strided reads (lane+32k)*19+r are conflict-free (gcd(19,32)=1).
// ---------------------------------------------------------------------------
__global__ void __launch_bounds__(TPB, 2)
score_kernel(const float* __restrict__ conv, float* __restrict__ out) {
    extern __shared__ __align__(16) char smem_raw[];
    const uint32_t s_base = (uint32_t)__cvta_generic_to_shared(smem_raw);
    // [0,16) full bars (8B each), [128,...) the two chunk buffers
    float* bufp = reinterpret_cast<float*>(smem_raw + 128);
    const uint32_t buf_base = s_base + 128;

    const int tid  = threadIdx.x;
    const int lane = tid & 31;
    const int r    = tid >> 5;               // warp id == relation id
    const int G    = gridDim.x;
    const int bid  = blockIdx.x;

    if (tid == 0) {
        asm volatile("mbarrier.init.shared.b64 [%0], 1;" :: "r"(s_base)     : "memory");
        asm volatile("mbarrier.init.shared.b64 [%0], 1;" :: "r"(s_base + 8) : "memory");
    }
    __syncthreads();

    // W values for this (lane, r), reused for every batch row
    float w[32];
#pragma unroll
    for (int k = 0; k < 32; ++k)
        w[k] = g_W[(lane + 32 * k) * RCNT + r];

    // prologue: chunks 0,1 (= both halves of row `bid`) into stages 0,1
    if (tid == 0) {
        tma_fill(s_base,     buf_base,        conv + (size_t)bid * ROW);
        tma_fill(s_base + 8, buf_base + CH_B, conv + (size_t)bid * ROW + CH_FL);
    }

    int t = 0;                                // running chunk counter
    for (int b = bid; b < BATCH; b += G) {
        float acc = 0.f;
#pragma unroll
        for (int c = 0; c < 2; ++c, ++t) {
            const int s = t & 1;
            bar_wait(s_base + s * 8, (uint32_t)((t >> 1) & 1));

            const float* p = bufp + s * CH_FL + lane * RCNT + r;
#pragma unroll
            for (int k = 0; k < 16; ++k)
                acc = fmaf(p[k * (32 * RCNT)], w[c * 16 + k], acc);

            __syncthreads();                  // all warps done reading stage s

            // refill stage s with chunk t+2 (next use: parity flips)
            const int tf = t + NSTAGE;
            const int bf = bid + (tf >> 1) * G;
            if (tid == 0 && bf < BATCH)
                tma_fill(s_base + s * 8, buf_base + s * CH_B,
                         conv + (size_t)bf * ROW + (tf & 1) * CH_FL);
        }

        // warp == relation: intra-warp reduce only
#pragma unroll
        for (int off = 16; off > 0; off >>= 1)
            acc += __shfl_down_sync(0xffffffffu, acc, off);
        if (lane == 0) out[(size_t)b * RCNT + r] = acc;
    }
}

// ---------------------------------------------------------------------------
extern "C" void kernel_launch(void* const* d_in, const int* in_sizes, int n_in,
                              void* d_out, int out_size) {
    const float* conv = nullptr;
    const float* Rm   = nullptr;
    const float* Um   = nullptr;
    for (int i = 0; i < n_in; ++i) {
        if (in_sizes[i] == BATCH * FNUM * RCNT)      conv = (const float*)d_in[i];
        else if (in_sizes[i] == RCNT * RDIM)         Rm   = (const float*)d_in[i];
        else if (in_sizes[i] == FNUM * RDIM)         Um   = (const float*)d_in[i];
    }
    float* out = (float*)d_out;

    static int attr_done = 0;
    if (!attr_done) {
        cudaFuncSetAttribute(score_kernel,
                             cudaFuncAttributeMaxDynamicSharedMemorySize, SMEM_B);
        attr_done = 1;
    }

    int dev = 0, nsm = 148;
    cudaGetDevice(&dev);
    cudaDeviceGetAttribute(&nsm, cudaDevAttrMultiProcessorCount, dev);

    compute_w_kernel<<<FNUM / 4, 256>>>(Um, Rm);
    score_kernel<<<2 * nsm, TPB, SMEM_B>>>(conv, out);
}